// round 16
// baseline (speedup 1.0000x reference)
#include <cuda_runtime.h>
#include <cuda_fp16.h>
#include <math.h>
#include <cstdint>

#define NNODES 20000
#define NEDGES 640000
#define DMODEL 512
#define NHEAD 8
#define DFFN 2048
#define DQKV 1536

// ================= scratch (no allocs allowed) =================
__device__ __align__(256) float g_o[(size_t)NNODES * DMODEL];
__device__ __align__(256) float g_x[(size_t)NNODES * DMODEL];
__device__ __align__(256) float g_y[(size_t)NNODES * DMODEL];
__device__ __align__(256) float g_e[(size_t)NEDGES * NHEAD];
__device__ int   g_rowptr[NNODES + 1];

__device__ __align__(256) __half g_h_h[(size_t)NNODES * DMODEL];
__device__ __align__(256) __half g_qkv[(size_t)NNODES * DQKV];   // q | k | v  fp16
__device__ __align__(256) __half g_a_h[(size_t)NNODES * DMODEL];
__device__ __align__(256) __half g_x_h[(size_t)NNODES * DMODEL];
__device__ __align__(256) __half g_f_h[(size_t)NNODES * DFFN];

__device__ __align__(256) __half g_wqkvT[DQKV * DMODEL];
__device__ __align__(256) __half g_woT[DMODEL * DMODEL];
__device__ __align__(256) __half g_w1T[DFFN * DMODEL];
__device__ __align__(256) __half g_w2T[DMODEL * DFFN];

// ================= low-level helpers (base ISA only) =================
__device__ __forceinline__ uint32_t smem_to_u32(const void* p) {
    uint32_t a;
    asm("{ .reg .u64 t; cvta.to.shared.u64 t, %1; cvt.u32.u64 %0, t; }" : "=r"(a) : "l"(p));
    return a;
}
__device__ __forceinline__ void cp_async16(uint32_t saddr, const void* g) {
    asm volatile("cp.async.cg.shared.global [%0], [%1], 16;" :: "r"(saddr), "l"(g));
}
#define CP_COMMIT() asm volatile("cp.async.commit_group;" ::: "memory")
#define CP_WAIT2()  asm volatile("cp.async.wait_group 2;"  ::: "memory")

__device__ __forceinline__ void ldsm_x4(uint32_t addr, uint32_t& r0, uint32_t& r1,
                                        uint32_t& r2, uint32_t& r3) {
    asm volatile("ldmatrix.sync.aligned.m8n8.x4.shared.b16 {%0,%1,%2,%3}, [%4];"
                 : "=r"(r0), "=r"(r1), "=r"(r2), "=r"(r3) : "r"(addr));
}
__device__ __forceinline__ void mma_f16(float c[4], const uint32_t a[4], const uint32_t b[2]) {
    asm volatile("mma.sync.aligned.m16n8k16.row.col.f32.f16.f16.f32 "
                 "{%0,%1,%2,%3}, {%4,%5,%6,%7}, {%8,%9}, {%0,%1,%2,%3};"
                 : "+f"(c[0]), "+f"(c[1]), "+f"(c[2]), "+f"(c[3])
                 : "r"(a[0]), "r"(a[1]), "r"(a[2]), "r"(a[3]), "r"(b[0]), "r"(b[1]));
}

// ================= CSR row pointers from sorted dst =================
__global__ void build_rowptr(const int* __restrict__ dst) {
    int i = blockIdx.x * blockDim.x + threadIdx.x;
    if (i > NNODES) return;
    int lo = 0, hi = NEDGES;
    while (lo < hi) { int mid = (lo + hi) >> 1; if (dst[mid] < i) lo = mid + 1; else hi = mid; }
    g_rowptr[i] = lo;
}

// ================= fp32 -> fp16 cast =================
__global__ void cast_f16(const float* __restrict__ x, __half* __restrict__ h, size_t n4) {
    size_t i = (size_t)blockIdx.x * blockDim.x + threadIdx.x;
    if (i >= n4) return;
    float4 v = ((const float4*)x)[i];
    __half2 a; a.x = __float2half_rn(v.x); a.y = __float2half_rn(v.y);
    __half2 b; b.x = __float2half_rn(v.z); b.y = __float2half_rn(v.w);
    ((__half2*)h)[i * 2 + 0] = a;
    ((__half2*)h)[i * 2 + 1] = b;
}

// ================= W[K,N] -> T[N,K] fp16 (tiled transpose+cast) =================
__global__ void transpose_cast(const float* __restrict__ W, __half* __restrict__ T,
                               int K, int N) {
    __shared__ float t[32][33];
    int n0 = blockIdx.x * 32, k0 = blockIdx.y * 32;
    int tx = threadIdx.x, ty = threadIdx.y;  // 32 x 8
#pragma unroll
    for (int j = 0; j < 32; j += 8)
        t[ty + j][tx] = W[(size_t)(k0 + ty + j) * N + n0 + tx];
    __syncthreads();
#pragma unroll
    for (int j = 0; j < 32; j += 8)
        T[(size_t)(n0 + ty + j) * K + k0 + tx] = __float2half_rn(t[tx][ty + j]);
}

// fused QKV transpose: grid.z selects Wq/Wk/Wv -> g_wqkvT rows [z*512, z*512+512)
__global__ void transpose_qkv(const float* __restrict__ Wq, const float* __restrict__ Wk,
                              const float* __restrict__ Wv, __half* __restrict__ T) {
    __shared__ float t[32][33];
    const float* W = (blockIdx.z == 0) ? Wq : (blockIdx.z == 1) ? Wk : Wv;
    __half* To = T + (size_t)blockIdx.z * 512 * DMODEL;
    int n0 = blockIdx.x * 32, k0 = blockIdx.y * 32;
    int tx = threadIdx.x, ty = threadIdx.y;
#pragma unroll
    for (int j = 0; j < 32; j += 8)
        t[ty + j][tx] = W[(size_t)(k0 + ty + j) * DMODEL + n0 + tx];
    __syncthreads();
#pragma unroll
    for (int j = 0; j < 32; j += 8)
        To[(size_t)(n0 + ty + j) * DMODEL + k0 + tx] = __float2half_rn(t[tx][ty + j]);
}

// ================= fp16 tensor-core GEMM (frozen R14 config) =================
// CTA tile 128x128x32, 4 warps (2x2, warp tile 64x64), 4-stage cp.async, 3 CTAs/SM.
#define STAGES 4
#define STAGE_BYTES 16384
#define GEMM_SMEM (STAGES * STAGE_BYTES)   // 64 KB

template<bool BIAS, bool RELU, bool OUTF32, bool OUTF16>
__global__ __launch_bounds__(128)
void gemm_mma(const __half* __restrict__ A, const __half* __restrict__ BT,
              const float* __restrict__ bias,
              float* __restrict__ C, __half* __restrict__ Ch,
              int M, int N, int K)
{
    extern __shared__ char smem[];
    const uint32_t sb = smem_to_u32(smem);
    const int tid = threadIdx.x, wid = tid >> 5, lid = tid & 31;
    const int wm = wid & 1, wn = wid >> 1;
    const int row0 = blockIdx.y * 128, col0 = blockIdx.x * 128;

    float c[4][8][4];
#pragma unroll
    for (int mi = 0; mi < 4; mi++)
#pragma unroll
        for (int ni = 0; ni < 8; ni++)
#pragma unroll
            for (int e = 0; e < 4; e++) c[mi][ni][e] = 0.f;

    auto load_stage = [&](int s, int k0) {
        const uint32_t base = sb + s * STAGE_BYTES;
#pragma unroll
        for (int u = 0; u < 4; u++) {
            int i = tid + u * 128;
            int r = i >> 2, kc = i & 3;
            int gr = row0 + r;  if (gr >= M) gr = M - 1;
            cp_async16(base + (uint32_t)((kc * 128 + r) * 16),
                       A + (size_t)gr * K + k0 + kc * 8);
        }
#pragma unroll
        for (int u = 0; u < 4; u++) {
            int j = tid + u * 128;
            int r = j >> 2, kc = j & 3;
            cp_async16(base + 8192 + (uint32_t)((kc * 128 + r) * 16),
                       BT + (size_t)(col0 + r) * K + k0 + kc * 8);
        }
    };

    auto compute_stage = [&](int s) {
        const uint32_t base = sb + s * STAGE_BYTES;
        const int lrow = lid & 7;
        const int lsel = lid >> 3;
        const int a_madd  = ((lsel & 1) << 3) + lrow;
        const int a_kcadd = lsel >> 1;
        const int b_nadd  = ((lsel >> 1) << 3) + lrow;
        const int b_kcadd = lsel & 1;
        for (int ks = 0; ks < 2; ks++) {
            uint32_t ah[4][4];
#pragma unroll
            for (int mi = 0; mi < 4; mi++) {
                int m = wm * 64 + mi * 16 + a_madd;
                int kc = ks * 2 + a_kcadd;
                ldsm_x4(base + (uint32_t)((kc * 128 + m) * 16),
                        ah[mi][0], ah[mi][1], ah[mi][2], ah[mi][3]);
            }
            uint32_t bh[8][2];
#pragma unroll
            for (int nq = 0; nq < 4; nq++) {
                int n = wn * 64 + nq * 16 + b_nadd;
                int kc = ks * 2 + b_kcadd;
                ldsm_x4(base + 8192 + (uint32_t)((kc * 128 + n) * 16),
                        bh[nq*2][0], bh[nq*2][1], bh[nq*2+1][0], bh[nq*2+1][1]);
            }
#pragma unroll
            for (int mi = 0; mi < 4; mi++)
#pragma unroll
                for (int ni = 0; ni < 8; ni++)
                    mma_f16(c[mi][ni], ah[mi], bh[ni]);
        }
    };

    const int nk = K >> 5;
#pragma unroll
    for (int s = 0; s < STAGES - 1; s++) { load_stage(s, s * 32); CP_COMMIT(); }

    for (int it = 0; it < nk; it++) {
        CP_WAIT2();
        __syncthreads();
        compute_stage(it % STAGES);
        int nxt = it + STAGES - 1;
        if (nxt < nk) load_stage(nxt % STAGES, nxt * 32);
        CP_COMMIT();
    }

    const int r_in = lid >> 2;
    const int c_in = (lid & 3) * 2;
#pragma unroll
    for (int mi = 0; mi < 4; mi++) {
#pragma unroll
        for (int half = 0; half < 2; half++) {
            int gr = row0 + wm * 64 + mi * 16 + half * 8 + r_in;
            if (gr >= M) continue;
#pragma unroll
            for (int ni = 0; ni < 8; ni++) {
                int gc = col0 + wn * 64 + ni * 8 + c_in;
                float v0 = c[mi][ni][half * 2 + 0];
                float v1 = c[mi][ni][half * 2 + 1];
                if (BIAS) { v0 += bias[gc]; v1 += bias[gc + 1]; }
                if (RELU) { v0 = fmaxf(v0, 0.f); v1 = fmaxf(v1, 0.f); }
                if (OUTF32)
                    *(float2*)(C + (size_t)gr * N + gc) = make_float2(v0, v1);
                if (OUTF16) {
                    __half2 hh; hh.x = __float2half_rn(v0); hh.y = __float2half_rn(v1);
                    *(__half2*)(Ch + (size_t)gr * N + gc) = hh;
                }
            }
        }
    }
}

// ================= edge scores (fp16 k gather, q cached in smem) =================
__device__ __forceinline__ float dot8h(uint4 a, uint4 b) {
    const __half2* pa = (const __half2*)&a;
    const __half2* pb = (const __half2*)&b;
    float s = 0.f;
#pragma unroll
    for (int i = 0; i < 4; i++) {
        float2 fa = __half22float2(pa[i]);
        float2 fb = __half22float2(pb[i]);
        s = fmaf(fa.x, fb.x, s);
        s = fmaf(fa.y, fb.y, s);
    }
    return s;
}
__global__ __launch_bounds__(128)
void edge_scores_csr(const int* __restrict__ src) {
    int node = blockIdx.x;
    int t = threadIdx.x;
    int beg = g_rowptr[node], end = g_rowptr[node + 1];

    __shared__ uint4 qs[64];
    if (t < 64) qs[t] = ((const uint4*)(g_qkv + (size_t)node * DQKV))[t];
    __syncthreads();

    int w = t >> 5, lane = t & 31;
    for (int e = beg + w; e < end; e += 4) {
        const uint4* kk = (const uint4*)(g_qkv + (size_t)src[e] * DQKV + DMODEL);
        float p0 = dot8h(kk[lane],      qs[lane]);
        float p1 = dot8h(kk[lane + 32], qs[lane + 32]);
#pragma unroll
        for (int off = 4; off; off >>= 1) {
            p0 += __shfl_xor_sync(0xffffffffu, p0, off);
            p1 += __shfl_xor_sync(0xffffffffu, p1, off);
        }
        if ((lane & 7) == 0) {
            float* out = g_e + (size_t)e * NHEAD;
            out[(lane >> 3)]     = p0 * 0.125f;
            out[4 + (lane >> 3)] = p1 * 0.125f;
        }
    }
}

// ================= per-node softmax + aggregation (smem weight cache) =================
#define WCAP 512   // cached edges per node; expected max degree ~60

__global__ __launch_bounds__(128)
void node_aggregate(const int* __restrict__ src) {
    int node = blockIdx.x;
    int t = threadIdx.x;
    int beg = g_rowptr[node], end = g_rowptr[node + 1];
    int deg = end - beg;

    __shared__ float s_m[NHEAD], s_rz[NHEAD];
    __shared__ float ws[WCAP * NHEAD];   // 16 KB weight cache

    // phase 1: per-head max & sum (16-thread groups, as before)
    int head = t >> 4, sub = t & 15;
    float mx = -INFINITY;
    for (int e = beg + sub; e < end; e += 16)
        mx = fmaxf(mx, g_e[(size_t)e * NHEAD + head]);
#pragma unroll
    for (int off = 8; off; off >>= 1)
        mx = fmaxf(mx, __shfl_xor_sync(0xffffffffu, mx, off));
    float sum = 0.f;
    for (int e = beg + sub; e < end; e += 16)
        sum += __expf(g_e[(size_t)e * NHEAD + head] - mx);
#pragma unroll
    for (int off = 8; off; off >>= 1)
        sum += __shfl_xor_sync(0xffffffffu, sum, off);
    if (sub == 0) { s_m[head] = mx; s_rz[head] = (deg > 0) ? (1.f / sum) : 0.f; }
    __syncthreads();

    // phase 2: weights into smem, coalesced over [deg x 8]
    {
        int total = ((deg < WCAP) ? deg : WCAP) * NHEAD;
        for (int i = t; i < total; i += 128) {
            int hh = i & 7;
            ws[i] = __expf(g_e[(size_t)beg * NHEAD + i] - s_m[hh]) * s_rz[hh];
        }
    }
    __syncthreads();

    // phase 3: weighted v aggregation (thread owns halves [4t,4t+4), head t>>4)
    int h2 = t >> 4;
    float m = s_m[h2], rz = s_rz[h2];
    float4 acc = make_float4(0.f, 0.f, 0.f, 0.f);

    int i = 0;
    for (; i + 1 < deg && i + 1 < WCAP; i += 2) {   // unroll 2 within cache
        float w0 = ws[i * NHEAD + h2];
        float w1 = ws[(i + 1) * NHEAD + h2];
        uint2 u0 = *(const uint2*)(g_qkv + (size_t)src[beg + i] * DQKV + 1024 + t * 4);
        uint2 u1 = *(const uint2*)(g_qkv + (size_t)src[beg + i + 1] * DQKV + 1024 + t * 4);
        float2 a01 = __half22float2(*(const __half2*)&u0.x);
        float2 a23 = __half22float2(*(const __half2*)&u0.y);
        float2 b01 = __half22float2(*(const __half2*)&u1.x);
        float2 b23 = __half22float2(*(const __half2*)&u1.y);
        acc.x = fmaf(w0, a01.x, fmaf(w1, b01.x, acc.x));
        acc.y = fmaf(w0, a01.y, fmaf(w1, b01.y, acc.y));
        acc.z = fmaf(w0, a23.x, fmaf(w1, b23.x, acc.z));
        acc.w = fmaf(w0, a23.y, fmaf(w1, b23.y, acc.w));
    }
    for (; i < deg; i++) {                           // tail + spill fallback
        float w = (i < WCAP) ? ws[i * NHEAD + h2]
                             : __expf(g_e[(size_t)(beg + i) * NHEAD + h2] - m) * rz;
        uint2 u = *(const uint2*)(g_qkv + (size_t)src[beg + i] * DQKV + 1024 + t * 4);
        float2 f01 = __half22float2(*(const __half2*)&u.x);
        float2 f23 = __half22float2(*(const __half2*)&u.y);
        acc.x = fmaf(w, f01.x, acc.x);
        acc.y = fmaf(w, f01.y, acc.y);
        acc.z = fmaf(w, f23.x, acc.z);
        acc.w = fmaf(w, f23.y, acc.w);
    }

    __half2 h01; h01.x = __float2half_rn(acc.x); h01.y = __float2half_rn(acc.y);
    __half2 h23; h23.x = __float2half_rn(acc.z); h23.y = __float2half_rn(acc.w);
    __half2* ph = (__half2*)(g_a_h + (size_t)node * DMODEL + t * 4);
    ph[0] = h01; ph[1] = h23;
}

// ================= residual + layernorm =================
template<bool EMIT_F16>
__global__ __launch_bounds__(128)
void residual_ln(const float* __restrict__ A, const float* __restrict__ B,
                 const float* __restrict__ gamma, const float* __restrict__ beta,
                 float* __restrict__ out, __half* __restrict__ oh)
{
    int row = blockIdx.x;
    int t = threadIdx.x;
    float4 va = ((const float4*)(A + (size_t)row * DMODEL))[t];
    float4 vb = ((const float4*)(B + (size_t)row * DMODEL))[t];
    float4 v = make_float4(va.x + vb.x, va.y + vb.y, va.z + vb.z, va.w + vb.w);

    __shared__ float sh1[4], sh2[4];
    float s = v.x + v.y + v.z + v.w;
#pragma unroll
    for (int off = 16; off; off >>= 1) s += __shfl_xor_sync(0xffffffffu, s, off);
    if ((t & 31) == 0) sh1[t >> 5] = s;
    __syncthreads();
    float mu = (sh1[0] + sh1[1] + sh1[2] + sh1[3]) * (1.f / DMODEL);

    float dx = v.x - mu, dy = v.y - mu, dz = v.z - mu, dw = v.w - mu;
    float ss = dx * dx + dy * dy + dz * dz + dw * dw;
#pragma unroll
    for (int off = 16; off; off >>= 1) ss += __shfl_xor_sync(0xffffffffu, ss, off);
    if ((t & 31) == 0) sh2[t >> 5] = ss;
    __syncthreads();
    float var = (sh2[0] + sh2[1] + sh2[2] + sh2[3]) * (1.f / DMODEL);
    float rstd = rsqrtf(var + 1e-5f);

    float4 g = ((const float4*)gamma)[t];
    float4 be = ((const float4*)beta)[t];
    float o0 = dx * rstd * g.x + be.x;
    float o1 = dy * rstd * g.y + be.y;
    float o2 = dz * rstd * g.z + be.z;
    float o3 = dw * rstd * g.w + be.w;
    ((float4*)(out + (size_t)row * DMODEL))[t] = make_float4(o0, o1, o2, o3);
    if (EMIT_F16) {
        __half2 h01; h01.x = __float2half_rn(o0); h01.y = __float2half_rn(o1);
        __half2 h23; h23.x = __float2half_rn(o2); h23.y = __float2half_rn(o3);
        __half2* ph = (__half2*)(oh + (size_t)row * DMODEL + t * 4);
        ph[0] = h01; ph[1] = h23;
    }
}

// ================= launch =================
extern "C" void kernel_launch(void* const* d_in, const int* in_sizes, int n_in,
                              void* d_out, int out_size)
{
    const float* h    = (const float*)d_in[0];
    const int*   src  = (const int*)d_in[1];
    const int*   dst  = (const int*)d_in[2];
    const float* Wq   = (const float*)d_in[3];
    const float* Wk   = (const float*)d_in[4];
    const float* Wv   = (const float*)d_in[5];
    const float* Wo   = (const float*)d_in[6];
    const float* ln1g = (const float*)d_in[7];
    const float* ln1b = (const float*)d_in[8];
    const float* ln2g = (const float*)d_in[9];
    const float* ln2b = (const float*)d_in[10];
    const float* W1   = (const float*)d_in[11];
    const float* b1   = (const float*)d_in[12];
    const float* W2   = (const float*)d_in[13];
    const float* b2   = (const float*)d_in[14];
    float* out = (float*)d_out;

    float *o, *x, *y;
    cudaGetSymbolAddress((void**)&o, g_o);
    cudaGetSymbolAddress((void**)&x, g_x);
    cudaGetSymbolAddress((void**)&y, g_y);
    __half *hh, *qkv, *ah, *xh, *fh;
    cudaGetSymbolAddress((void**)&hh, g_h_h);
    cudaGetSymbolAddress((void**)&qkv, g_qkv);
    cudaGetSymbolAddress((void**)&ah, g_a_h);
    cudaGetSymbolAddress((void**)&xh, g_x_h);
    cudaGetSymbolAddress((void**)&fh, g_f_h);
    __half *wqkvT, *woT, *w1T, *w2T;
    cudaGetSymbolAddress((void**)&wqkvT, g_wqkvT);
    cudaGetSymbolAddress((void**)&woT, g_woT);
    cudaGetSymbolAddress((void**)&w1T, g_w1T);
    cudaGetSymbolAddress((void**)&w2T, g_w2T);

    cudaFuncSetAttribute(gemm_mma<false, false, false, true>,
                         cudaFuncAttributeMaxDynamicSharedMemorySize, GEMM_SMEM);
    cudaFuncSetAttribute(gemm_mma<false, false, true,  false>,
                         cudaFuncAttributeMaxDynamicSharedMemorySize, GEMM_SMEM);
    cudaFuncSetAttribute(gemm_mma<true,  true,  false, true>,
                         cudaFuncAttributeMaxDynamicSharedMemorySize, GEMM_SMEM);
    cudaFuncSetAttribute(gemm_mma<true,  false, true,  false>,
                         cudaFuncAttributeMaxDynamicSharedMemorySize, GEMM_SMEM);

    const int MB = (NNODES + 127) / 128;           // 157
    const dim3 gqkv(DQKV / 128, MB);               // (12, 157)
    const dim3 g512(DMODEL / 128, MB);             // (4, 157)
    const dim3 gff(DFFN / 128, MB);                // (16, 157)

    // launch order: node_aggregate is launch #6 (profiled by ncu -s 5 -c 1)
    build_rowptr<<<(NNODES + 256) / 256, 256>>>(dst);                                  // 1
    cast_f16<<<(NNODES * DMODEL / 4 + 255) / 256, 256>>>(h, hh,
                                                         (size_t)NNODES * DMODEL / 4); // 2
    transpose_qkv<<<dim3(16, 16, 3), dim3(32, 8)>>>(Wq, Wk, Wv, wqkvT);                // 3
    gemm_mma<false, false, false, true><<<gqkv, 128, GEMM_SMEM>>>(
        hh, wqkvT, nullptr, nullptr, qkv, NNODES, DQKV, DMODEL);                       // 4
    edge_scores_csr<<<NNODES, 128>>>(src);                                             // 5
    node_aggregate<<<NNODES, 128>>>(src);                                              // 6 <- profiled

    transpose_cast<<<dim3(16, 16), dim3(32, 8)>>>(Wo, woT, DMODEL, DMODEL);
    transpose_cast<<<dim3(DFFN / 32, 16), dim3(32, 8)>>>(W1, w1T, DMODEL, DFFN);
    transpose_cast<<<dim3(16, DFFN / 32), dim3(32, 8)>>>(W2, w2T, DFFN, DMODEL);

    gemm_mma<false, false, true, false><<<g512, 128, GEMM_SMEM>>>(
        ah, woT, nullptr, o, nullptr, NNODES, DMODEL, DMODEL);
    residual_ln<true><<<NNODES, 128>>>(h, o, ln1g, ln1b, x, xh);

    gemm_mma<true, true, false, true><<<gff, 128, GEMM_SMEM>>>(
        xh, w1T, b1, nullptr, fh, NNODES, DFFN, DMODEL);
    gemm_mma<true, false, true, false><<<g512, 128, GEMM_SMEM>>>(
        fh, w2T, b2, y, nullptr, NNODES, DMODEL, DFFN);

    residual_ln<false><<<NNODES, 128>>>(x, y, ln2g, ln2b, out, nullptr);
}

// round 17
// speedup vs baseline: 1.0129x; 1.0129x over previous
#include <cuda_runtime.h>
#include <cuda_fp16.h>
#include <math.h>
#include <cstdint>

#define NNODES 20000
#define NEDGES 640000
#define DMODEL 512
#define NHEAD 8
#define DFFN 2048
#define DQKV 1536

// ================= scratch (no allocs allowed) =================
__device__ __align__(256) float g_o[2 * (size_t)NNODES * DMODEL];   // split-K partials
__device__ __align__(256) float g_x[(size_t)NNODES * DMODEL];
__device__ __align__(256) float g_y[2 * (size_t)NNODES * DMODEL];   // split-K partials
__device__ __align__(256) float g_e[(size_t)NEDGES * NHEAD];
__device__ int   g_rowptr[NNODES + 1];

__device__ __align__(256) __half g_h_h[(size_t)NNODES * DMODEL];
__device__ __align__(256) __half g_qkv[(size_t)NNODES * DQKV];   // q | k | v  fp16
__device__ __align__(256) __half g_a_h[(size_t)NNODES * DMODEL];
__device__ __align__(256) __half g_x_h[(size_t)NNODES * DMODEL];
__device__ __align__(256) __half g_f_h[(size_t)NNODES * DFFN];

__device__ __align__(256) __half g_wqkvT[DQKV * DMODEL];
__device__ __align__(256) __half g_woT[DMODEL * DMODEL];
__device__ __align__(256) __half g_w1T[DFFN * DMODEL];
__device__ __align__(256) __half g_w2T[DMODEL * DFFN];

// ================= low-level helpers (base ISA only) =================
__device__ __forceinline__ uint32_t smem_to_u32(const void* p) {
    uint32_t a;
    asm("{ .reg .u64 t; cvta.to.shared.u64 t, %1; cvt.u32.u64 %0, t; }" : "=r"(a) : "l"(p));
    return a;
}
__device__ __forceinline__ void cp_async16(uint32_t saddr, const void* g) {
    asm volatile("cp.async.cg.shared.global [%0], [%1], 16;" :: "r"(saddr), "l"(g));
}
#define CP_COMMIT() asm volatile("cp.async.commit_group;" ::: "memory")
#define CP_WAIT2()  asm volatile("cp.async.wait_group 2;"  ::: "memory")

__device__ __forceinline__ void ldsm_x4(uint32_t addr, uint32_t& r0, uint32_t& r1,
                                        uint32_t& r2, uint32_t& r3) {
    asm volatile("ldmatrix.sync.aligned.m8n8.x4.shared.b16 {%0,%1,%2,%3}, [%4];"
                 : "=r"(r0), "=r"(r1), "=r"(r2), "=r"(r3) : "r"(addr));
}
__device__ __forceinline__ void mma_f16(float c[4], const uint32_t a[4], const uint32_t b[2]) {
    asm volatile("mma.sync.aligned.m16n8k16.row.col.f32.f16.f16.f32 "
                 "{%0,%1,%2,%3}, {%4,%5,%6,%7}, {%8,%9}, {%0,%1,%2,%3};"
                 : "+f"(c[0]), "+f"(c[1]), "+f"(c[2]), "+f"(c[3])
                 : "r"(a[0]), "r"(a[1]), "r"(a[2]), "r"(a[3]), "r"(b[0]), "r"(b[1]));
}

// ================= CSR row pointers from sorted dst =================
__global__ void build_rowptr(const int* __restrict__ dst) {
    int i = blockIdx.x * blockDim.x + threadIdx.x;
    if (i > NNODES) return;
    int lo = 0, hi = NEDGES;
    while (lo < hi) { int mid = (lo + hi) >> 1; if (dst[mid] < i) lo = mid + 1; else hi = mid; }
    g_rowptr[i] = lo;
}

// ================= fp32 -> fp16 cast =================
__global__ void cast_f16(const float* __restrict__ x, __half* __restrict__ h, size_t n4) {
    size_t i = (size_t)blockIdx.x * blockDim.x + threadIdx.x;
    if (i >= n4) return;
    float4 v = ((const float4*)x)[i];
    __half2 a; a.x = __float2half_rn(v.x); a.y = __float2half_rn(v.y);
    __half2 b; b.x = __float2half_rn(v.z); b.y = __float2half_rn(v.w);
    ((__half2*)h)[i * 2 + 0] = a;
    ((__half2*)h)[i * 2 + 1] = b;
}

// ================= W[K,N] -> T[N,K] fp16 (tiled transpose+cast) =================
__global__ void transpose_cast(const float* __restrict__ W, __half* __restrict__ T,
                               int K, int N) {
    __shared__ float t[32][33];
    int n0 = blockIdx.x * 32, k0 = blockIdx.y * 32;
    int tx = threadIdx.x, ty = threadIdx.y;  // 32 x 8
#pragma unroll
    for (int j = 0; j < 32; j += 8)
        t[ty + j][tx] = W[(size_t)(k0 + ty + j) * N + n0 + tx];
    __syncthreads();
#pragma unroll
    for (int j = 0; j < 32; j += 8)
        T[(size_t)(n0 + ty + j) * K + k0 + tx] = __float2half_rn(t[tx][ty + j]);
}

// fused QKV transpose: grid.z selects Wq/Wk/Wv -> g_wqkvT rows [z*512, z*512+512)
__global__ void transpose_qkv(const float* __restrict__ Wq, const float* __restrict__ Wk,
                              const float* __restrict__ Wv, __half* __restrict__ T) {
    __shared__ float t[32][33];
    const float* W = (blockIdx.z == 0) ? Wq : (blockIdx.z == 1) ? Wk : Wv;
    __half* To = T + (size_t)blockIdx.z * 512 * DMODEL;
    int n0 = blockIdx.x * 32, k0 = blockIdx.y * 32;
    int tx = threadIdx.x, ty = threadIdx.y;
#pragma unroll
    for (int j = 0; j < 32; j += 8)
        t[ty + j][tx] = W[(size_t)(k0 + ty + j) * DMODEL + n0 + tx];
    __syncthreads();
#pragma unroll
    for (int j = 0; j < 32; j += 8)
        To[(size_t)(n0 + ty + j) * DMODEL + k0 + tx] = __float2half_rn(t[tx][ty + j]);
}

// ================= fp16 tensor-core GEMM (frozen R14 core + split-K) =================
// CTA tile 128x128x32, 4 warps (2x2, warp tile 64x64), 4-stage cp.async, 3 CTAs/SM.
// blockIdx.z = split-K slab: A/BT column offset z*K, fp32 C offset z*M*N.
// K = slab length, ldk = full row stride of A and BT.
#define STAGES 4
#define STAGE_BYTES 16384
#define GEMM_SMEM (STAGES * STAGE_BYTES)   // 64 KB

template<bool BIAS, bool RELU, bool OUTF32, bool OUTF16>
__global__ __launch_bounds__(128)
void gemm_mma(const __half* __restrict__ A, const __half* __restrict__ BT,
              const float* __restrict__ bias,
              float* __restrict__ C, __half* __restrict__ Ch,
              int M, int N, int K, int ldk)
{
    extern __shared__ char smem[];
    const uint32_t sb = smem_to_u32(smem);
    const int tid = threadIdx.x, wid = tid >> 5, lid = tid & 31;
    const int wm = wid & 1, wn = wid >> 1;
    const int row0 = blockIdx.y * 128, col0 = blockIdx.x * 128;
    const int zz = blockIdx.z;
    A  += (size_t)zz * K;
    BT += (size_t)zz * K;
    if (OUTF32) C += (size_t)zz * M * N;
    const bool do_bias = BIAS && (zz == 0);

    float c[4][8][4];
#pragma unroll
    for (int mi = 0; mi < 4; mi++)
#pragma unroll
        for (int ni = 0; ni < 8; ni++)
#pragma unroll
            for (int e = 0; e < 4; e++) c[mi][ni][e] = 0.f;

    auto load_stage = [&](int s, int k0) {
        const uint32_t base = sb + s * STAGE_BYTES;
#pragma unroll
        for (int u = 0; u < 4; u++) {
            int i = tid + u * 128;
            int r = i >> 2, kc = i & 3;
            int gr = row0 + r;  if (gr >= M) gr = M - 1;
            cp_async16(base + (uint32_t)((kc * 128 + r) * 16),
                       A + (size_t)gr * ldk + k0 + kc * 8);
        }
#pragma unroll
        for (int u = 0; u < 4; u++) {
            int j = tid + u * 128;
            int r = j >> 2, kc = j & 3;
            cp_async16(base + 8192 + (uint32_t)((kc * 128 + r) * 16),
                       BT + (size_t)(col0 + r) * ldk + k0 + kc * 8);
        }
    };

    auto compute_stage = [&](int s) {
        const uint32_t base = sb + s * STAGE_BYTES;
        const int lrow = lid & 7;
        const int lsel = lid >> 3;
        const int a_madd  = ((lsel & 1) << 3) + lrow;
        const int a_kcadd = lsel >> 1;
        const int b_nadd  = ((lsel >> 1) << 3) + lrow;
        const int b_kcadd = lsel & 1;
        for (int ks = 0; ks < 2; ks++) {
            uint32_t ah[4][4];
#pragma unroll
            for (int mi = 0; mi < 4; mi++) {
                int m = wm * 64 + mi * 16 + a_madd;
                int kc = ks * 2 + a_kcadd;
                ldsm_x4(base + (uint32_t)((kc * 128 + m) * 16),
                        ah[mi][0], ah[mi][1], ah[mi][2], ah[mi][3]);
            }
            uint32_t bh[8][2];
#pragma unroll
            for (int nq = 0; nq < 4; nq++) {
                int n = wn * 64 + nq * 16 + b_nadd;
                int kc = ks * 2 + b_kcadd;
                ldsm_x4(base + 8192 + (uint32_t)((kc * 128 + n) * 16),
                        bh[nq*2][0], bh[nq*2][1], bh[nq*2+1][0], bh[nq*2+1][1]);
            }
#pragma unroll
            for (int mi = 0; mi < 4; mi++)
#pragma unroll
                for (int ni = 0; ni < 8; ni++)
                    mma_f16(c[mi][ni], ah[mi], bh[ni]);
        }
    };

    const int nk = K >> 5;
#pragma unroll
    for (int s = 0; s < STAGES - 1; s++) { load_stage(s, s * 32); CP_COMMIT(); }

    for (int it = 0; it < nk; it++) {
        CP_WAIT2();
        __syncthreads();
        compute_stage(it % STAGES);
        int nxt = it + STAGES - 1;
        if (nxt < nk) load_stage(nxt % STAGES, nxt * 32);
        CP_COMMIT();
    }

    const int r_in = lid >> 2;
    const int c_in = (lid & 3) * 2;
#pragma unroll
    for (int mi = 0; mi < 4; mi++) {
#pragma unroll
        for (int half = 0; half < 2; half++) {
            int gr = row0 + wm * 64 + mi * 16 + half * 8 + r_in;
            if (gr >= M) continue;
#pragma unroll
            for (int ni = 0; ni < 8; ni++) {
                int gc = col0 + wn * 64 + ni * 8 + c_in;
                float v0 = c[mi][ni][half * 2 + 0];
                float v1 = c[mi][ni][half * 2 + 1];
                if (BIAS) { if (do_bias) { v0 += bias[gc]; v1 += bias[gc + 1]; } }
                if (RELU) { v0 = fmaxf(v0, 0.f); v1 = fmaxf(v1, 0.f); }
                if (OUTF32)
                    *(float2*)(C + (size_t)gr * N + gc) = make_float2(v0, v1);
                if (OUTF16) {
                    __half2 hh; hh.x = __float2half_rn(v0); hh.y = __float2half_rn(v1);
                    *(__half2*)(Ch + (size_t)gr * N + gc) = hh;
                }
            }
        }
    }
}

// ================= edge scores (fp16 k gather, q cached in smem) =================
__device__ __forceinline__ float dot8h(uint4 a, uint4 b) {
    const __half2* pa = (const __half2*)&a;
    const __half2* pb = (const __half2*)&b;
    float s = 0.f;
#pragma unroll
    for (int i = 0; i < 4; i++) {
        float2 fa = __half22float2(pa[i]);
        float2 fb = __half22float2(pb[i]);
        s = fmaf(fa.x, fb.x, s);
        s = fmaf(fa.y, fb.y, s);
    }
    return s;
}
__global__ __launch_bounds__(128)
void edge_scores_csr(const int* __restrict__ src) {
    int node = blockIdx.x;
    int t = threadIdx.x;
    int beg = g_rowptr[node], end = g_rowptr[node + 1];

    __shared__ uint4 qs[64];
    if (t < 64) qs[t] = ((const uint4*)(g_qkv + (size_t)node * DQKV))[t];
    __syncthreads();

    int w = t >> 5, lane = t & 31;
    for (int e = beg + w; e < end; e += 4) {
        const uint4* kk = (const uint4*)(g_qkv + (size_t)src[e] * DQKV + DMODEL);
        float p0 = dot8h(kk[lane],      qs[lane]);
        float p1 = dot8h(kk[lane + 32], qs[lane + 32]);
#pragma unroll
        for (int off = 4; off; off >>= 1) {
            p0 += __shfl_xor_sync(0xffffffffu, p0, off);
            p1 += __shfl_xor_sync(0xffffffffu, p1, off);
        }
        if ((lane & 7) == 0) {
            float* out = g_e + (size_t)e * NHEAD;
            out[(lane >> 3)]     = p0 * 0.125f;
            out[4 + (lane >> 3)] = p1 * 0.125f;
        }
    }
}

// ================= per-node softmax + aggregation (R14 version) =================
__global__ __launch_bounds__(128)
void node_aggregate(const int* __restrict__ src) {
    int node = blockIdx.x;
    int t = threadIdx.x;
    int beg = g_rowptr[node], end = g_rowptr[node + 1];

    __shared__ float s_m[NHEAD], s_rz[NHEAD];
    int head = t >> 4, sub = t & 15;
    float mx = -INFINITY;
    for (int e = beg + sub; e < end; e += 16)
        mx = fmaxf(mx, g_e[(size_t)e * NHEAD + head]);
#pragma unroll
    for (int off = 8; off; off >>= 1)
        mx = fmaxf(mx, __shfl_xor_sync(0xffffffffu, mx, off));
    float sum = 0.f;
    for (int e = beg + sub; e < end; e += 16)
        sum += __expf(g_e[(size_t)e * NHEAD + head] - mx);
#pragma unroll
    for (int off = 8; off; off >>= 1)
        sum += __shfl_xor_sync(0xffffffffu, sum, off);
    if (sub == 0) { s_m[head] = mx; s_rz[head] = (end > beg) ? (1.f / sum) : 0.f; }
    __syncthreads();

    int h2 = t >> 4;
    float m = s_m[h2], rz = s_rz[h2];
    float4 acc = make_float4(0.f, 0.f, 0.f, 0.f);
    for (int e = beg; e < end; e++) {
        float w = __expf(g_e[(size_t)e * NHEAD + h2] - m) * rz;
        uint2 u = *(const uint2*)(g_qkv + (size_t)src[e] * DQKV + 1024 + t * 4);
        float2 f01 = __half22float2(*(const __half2*)&u.x);
        float2 f23 = __half22float2(*(const __half2*)&u.y);
        acc.x = fmaf(w, f01.x, acc.x);
        acc.y = fmaf(w, f01.y, acc.y);
        acc.z = fmaf(w, f23.x, acc.z);
        acc.w = fmaf(w, f23.y, acc.w);
    }
    __half2 h01; h01.x = __float2half_rn(acc.x); h01.y = __float2half_rn(acc.y);
    __half2 h23; h23.x = __float2half_rn(acc.z); h23.y = __float2half_rn(acc.w);
    __half2* ph = (__half2*)(g_a_h + (size_t)node * DMODEL + t * 4);
    ph[0] = h01; ph[1] = h23;
}

// ================= residual + layernorm (3-way sum: A + B1 + B2) =================
template<bool EMIT_F16>
__global__ __launch_bounds__(128)
void residual_ln3(const float* __restrict__ A, const float* __restrict__ B1,
                  const float* __restrict__ B2,
                  const float* __restrict__ gamma, const float* __restrict__ beta,
                  float* __restrict__ out, __half* __restrict__ oh)
{
    int row = blockIdx.x;
    int t = threadIdx.x;
    float4 va = ((const float4*)(A  + (size_t)row * DMODEL))[t];
    float4 vb = ((const float4*)(B1 + (size_t)row * DMODEL))[t];
    float4 vc = ((const float4*)(B2 + (size_t)row * DMODEL))[t];
    float4 v = make_float4(va.x + vb.x + vc.x, va.y + vb.y + vc.y,
                           va.z + vb.z + vc.z, va.w + vb.w + vc.w);

    __shared__ float sh1[4], sh2[4];
    float s = v.x + v.y + v.z + v.w;
#pragma unroll
    for (int off = 16; off; off >>= 1) s += __shfl_xor_sync(0xffffffffu, s, off);
    if ((t & 31) == 0) sh1[t >> 5] = s;
    __syncthreads();
    float mu = (sh1[0] + sh1[1] + sh1[2] + sh1[3]) * (1.f / DMODEL);

    float dx = v.x - mu, dy = v.y - mu, dz = v.z - mu, dw = v.w - mu;
    float ss = dx * dx + dy * dy + dz * dz + dw * dw;
#pragma unroll
    for (int off = 16; off; off >>= 1) ss += __shfl_xor_sync(0xffffffffu, ss, off);
    if ((t & 31) == 0) sh2[t >> 5] = ss;
    __syncthreads();
    float var = (sh2[0] + sh2[1] + sh2[2] + sh2[3]) * (1.f / DMODEL);
    float rstd = rsqrtf(var + 1e-5f);

    float4 g = ((const float4*)gamma)[t];
    float4 be = ((const float4*)beta)[t];
    float o0 = dx * rstd * g.x + be.x;
    float o1 = dy * rstd * g.y + be.y;
    float o2 = dz * rstd * g.z + be.z;
    float o3 = dw * rstd * g.w + be.w;
    ((float4*)(out + (size_t)row * DMODEL))[t] = make_float4(o0, o1, o2, o3);
    if (EMIT_F16) {
        __half2 h01; h01.x = __float2half_rn(o0); h01.y = __float2half_rn(o1);
        __half2 h23; h23.x = __float2half_rn(o2); h23.y = __float2half_rn(o3);
        __half2* ph = (__half2*)(oh + (size_t)row * DMODEL + t * 4);
        ph[0] = h01; ph[1] = h23;
    }
}

// ================= launch =================
extern "C" void kernel_launch(void* const* d_in, const int* in_sizes, int n_in,
                              void* d_out, int out_size)
{
    const float* h    = (const float*)d_in[0];
    const int*   src  = (const int*)d_in[1];
    const int*   dst  = (const int*)d_in[2];
    const float* Wq   = (const float*)d_in[3];
    const float* Wk   = (const float*)d_in[4];
    const float* Wv   = (const float*)d_in[5];
    const float* Wo   = (const float*)d_in[6];
    const float* ln1g = (const float*)d_in[7];
    const float* ln1b = (const float*)d_in[8];
    const float* ln2g = (const float*)d_in[9];
    const float* ln2b = (const float*)d_in[10];
    const float* W1   = (const float*)d_in[11];
    const float* b1   = (const float*)d_in[12];
    const float* W2   = (const float*)d_in[13];
    const float* b2   = (const float*)d_in[14];
    float* out = (float*)d_out;

    float *o, *x, *y;
    cudaGetSymbolAddress((void**)&o, g_o);
    cudaGetSymbolAddress((void**)&x, g_x);
    cudaGetSymbolAddress((void**)&y, g_y);
    __half *hh, *qkv, *ah, *xh, *fh;
    cudaGetSymbolAddress((void**)&hh, g_h_h);
    cudaGetSymbolAddress((void**)&qkv, g_qkv);
    cudaGetSymbolAddress((void**)&ah, g_a_h);
    cudaGetSymbolAddress((void**)&xh, g_x_h);
    cudaGetSymbolAddress((void**)&fh, g_f_h);
    __half *wqkvT, *woT, *w1T, *w2T;
    cudaGetSymbolAddress((void**)&wqkvT, g_wqkvT);
    cudaGetSymbolAddress((void**)&woT, g_woT);
    cudaGetSymbolAddress((void**)&w1T, g_w1T);
    cudaGetSymbolAddress((void**)&w2T, g_w2T);

    cudaFuncSetAttribute(gemm_mma<false, false, false, true>,
                         cudaFuncAttributeMaxDynamicSharedMemorySize, GEMM_SMEM);
    cudaFuncSetAttribute(gemm_mma<false, false, true,  false>,
                         cudaFuncAttributeMaxDynamicSharedMemorySize, GEMM_SMEM);
    cudaFuncSetAttribute(gemm_mma<true,  true,  false, true>,
                         cudaFuncAttributeMaxDynamicSharedMemorySize, GEMM_SMEM);
    cudaFuncSetAttribute(gemm_mma<true,  false, true,  false>,
                         cudaFuncAttributeMaxDynamicSharedMemorySize, GEMM_SMEM);

    const size_t MN = (size_t)NNODES * DMODEL;
    const int MB = (NNODES + 127) / 128;             // 157
    const dim3 gqkv(DQKV / 128, MB, 1);              // (12, 157)
    const dim3 g512s(DMODEL / 128, MB, 2);           // (4, 157, 2) split-K
    const dim3 gff(DFFN / 128, MB, 1);               // (16, 157)

    build_rowptr<<<(NNODES + 256) / 256, 256>>>(dst);                                  // 1
    cast_f16<<<(NNODES * DMODEL / 4 + 255) / 256, 256>>>(h, hh,
                                                         (size_t)NNODES * DMODEL / 4); // 2
    transpose_qkv<<<dim3(16, 16, 3), dim3(32, 8)>>>(Wq, Wk, Wv, wqkvT);                // 3
    gemm_mma<false, false, false, true><<<gqkv, 128, GEMM_SMEM>>>(
        hh, wqkvT, nullptr, nullptr, qkv, NNODES, DQKV, DMODEL, DMODEL);               // 4
    edge_scores_csr<<<NNODES, 128>>>(src);                                             // 5
    node_aggregate<<<NNODES, 128>>>(src);                                              // 6

    transpose_cast<<<dim3(16, 16), dim3(32, 8)>>>(Wo, woT, DMODEL, DMODEL);
    transpose_cast<<<dim3(DFFN / 32, 16), dim3(32, 8)>>>(W1, w1T, DMODEL, DFFN);
    transpose_cast<<<dim3(16, DFFN / 32), dim3(32, 8)>>>(W2, w2T, DFFN, DMODEL);

    // Wo GEMM: split-K=2 (each half K=256), partials o[0], o[MN]
    gemm_mma<false, false, true, false><<<g512s, 128, GEMM_SMEM>>>(
        ah, woT, nullptr, o, nullptr, NNODES, DMODEL, 256, DMODEL);
    residual_ln3<true><<<NNODES, 128>>>(h, o, o + MN, ln1g, ln1b, x, xh);

    gemm_mma<true, true, false, true><<<gff, 128, GEMM_SMEM>>>(
        xh, w1T, b1, nullptr, fh, NNODES, DFFN, DMODEL, DMODEL);

    // FFN2 GEMM: split-K=2 (each half K=1024), partials y[0], y[MN]; bias on z=0
    gemm_mma<true, false, true, false><<<g512s, 128, GEMM_SMEM>>>(
        fh, w2T, b2, y, nullptr, NNODES, DMODEL, 1024, DFFN);

    residual_ln3<false><<<NNODES, 128>>>(x, y, y + MN, ln2g, ln2b, out, nullptr);
}